// round 1
// baseline (speedup 1.0000x reference)
#include <cuda_runtime.h>
#include <math.h>

// Problem constants (cWCT_36739150250149): B=8, N=512, H=W=64 -> M=4096
#define BB     8
#define NCH    512
#define MPIX   4096
#define NMAT   16               // 16 covariance matrices: [0..7]=content, [8..15]=style
#define MATSZ  (512*512)
#define TPAD   132              // padded smem stride for transposed tiles

// ---------------- device scratch (static, no allocations) ----------------
__device__ float g_cov [NMAT * MATSZ];   // 16 MB : Gram/cov -> Cholesky L in place
__device__ float g_inv [8    * MATSZ];   //  8 MB : inv(Lc)
__device__ float g_T   [8    * MATSZ];   //  8 MB : T = Ls * inv(Lc)
__device__ float g_mean[NMAT * 512];
__device__ float g_bias[8    * 512];

// ---------------- 1) row means ----------------
__global__ void mean_kernel(const float* __restrict__ cont, const float* __restrict__ styl) {
    const int idx = blockIdx.x;                       // 0..8191  (w*4096 + b*512 + n)
    const float* src = (idx < 4096 ? cont : styl) + (size_t)(idx & 4095) * MPIX;
    float s = 0.f;
    for (int k = threadIdx.x; k < MPIX; k += 256) s += src[k];
    __shared__ float red[256];
    red[threadIdx.x] = s;
    __syncthreads();
    for (int o = 128; o >= 32; o >>= 1) {
        if (threadIdx.x < o) red[threadIdx.x] += red[threadIdx.x + o];
        __syncthreads();
    }
    if (threadIdx.x < 32) {
        float v = red[threadIdx.x];
        #pragma unroll
        for (int o = 16; o; o >>= 1) v += __shfl_xor_sync(0xffffffffu, v, o);
        if (threadIdx.x == 0) g_mean[idx] = v * (1.f / (float)MPIX);
    }
}

// ---------------- 2) Gram -> covariance (NT GEMM, symmetric lower tiles) ----------------
__global__ void __launch_bounds__(256) gram_kernel(const float* __restrict__ cont,
                                                   const float* __restrict__ styl) {
    const int bi = blockIdx.x, bj = blockIdx.y, mat = blockIdx.z;
    if (bi < bj) return;
    const float* X = (mat < 8 ? cont : styl) + (size_t)(mat & 7) * (512ull * 4096ull);

    __shared__ float As[2][16][TPAD];
    __shared__ float Bs[2][16][TPAD];

    const int t    = threadIdx.x;
    const int lrow = t & 127;
    const int kg   = t >> 7;                 // 0/1
    const float* aptr = X + (size_t)(bi * 128 + lrow) * MPIX + kg * 8;
    const float* bptr = X + (size_t)(bj * 128 + lrow) * MPIX + kg * 8;
    const int m0 = (t >> 4) << 3, n0 = (t & 15) << 3;

    float acc[8][8];
    #pragma unroll
    for (int i = 0; i < 8; ++i)
        #pragma unroll
        for (int j = 0; j < 8; ++j) acc[i][j] = 0.f;

    const int NT = MPIX / 16;
    // prefetch tile 0
    {
        float av[8], bv[8];
        *(float4*)&av[0] = *(const float4*)(aptr);
        *(float4*)&av[4] = *(const float4*)(aptr + 4);
        *(float4*)&bv[0] = *(const float4*)(bptr);
        *(float4*)&bv[4] = *(const float4*)(bptr + 4);
        const int kb = kg * 8;
        #pragma unroll
        for (int c = 0; c < 8; ++c) { As[0][kb + c][lrow] = av[c]; Bs[0][kb + c][lrow] = bv[c]; }
    }
    __syncthreads();

    for (int kt = 0; kt < NT; ++kt) {
        const int cur = kt & 1;
        if (kt + 1 < NT) {
            float av[8], bv[8];
            const float* ap = aptr + (kt + 1) * 16;
            const float* bp = bptr + (kt + 1) * 16;
            *(float4*)&av[0] = *(const float4*)(ap);
            *(float4*)&av[4] = *(const float4*)(ap + 4);
            *(float4*)&bv[0] = *(const float4*)(bp);
            *(float4*)&bv[4] = *(const float4*)(bp + 4);
            const int kb = kg * 8, nb = cur ^ 1;
            #pragma unroll
            for (int c = 0; c < 8; ++c) { As[nb][kb + c][lrow] = av[c]; Bs[nb][kb + c][lrow] = bv[c]; }
        }
        #pragma unroll
        for (int k = 0; k < 16; ++k) {
            float a[8], b[8];
            *(float4*)&a[0] = *(const float4*)&As[cur][k][m0];
            *(float4*)&a[4] = *(const float4*)&As[cur][k][m0 + 4];
            *(float4*)&b[0] = *(const float4*)&Bs[cur][k][n0];
            *(float4*)&b[4] = *(const float4*)&Bs[cur][k][n0 + 4];
            #pragma unroll
            for (int i = 0; i < 8; ++i)
                #pragma unroll
                for (int j = 0; j < 8; ++j) acc[i][j] += a[i] * b[j];
        }
        __syncthreads();
    }

    // epilogue: cov = (gram - M*mi*mj)/(M-1); write (i,j) and its mirror
    const float* mrow = g_mean + mat * 512;
    float mi[8], mj[8];
    #pragma unroll
    for (int i = 0; i < 8; ++i) mi[i] = mrow[bi * 128 + m0 + i];
    #pragma unroll
    for (int j = 0; j < 8; ++j) mj[j] = mrow[bj * 128 + n0 + j];
    float* C = g_cov + (size_t)mat * MATSZ;
    const float invm1 = 1.f / (float)(MPIX - 1);
    #pragma unroll
    for (int i = 0; i < 8; ++i) {
        const int gi = bi * 128 + m0 + i;
        #pragma unroll
        for (int j = 0; j < 8; ++j) {
            const int gj = bj * 128 + n0 + j;
            const float v = (acc[i][j] - (float)MPIX * mi[i] * mj[j]) * invm1;
            C[(size_t)gi * 512 + gj] = v;
            C[(size_t)gj * 512 + gi] = v;
        }
    }
}

// ---------------- 3) blocked Cholesky (bs = 64), in place on g_cov lower ----------------
__global__ void chol_diag(int s) {
    const int mat = blockIdx.x;
    float* A = g_cov + (size_t)mat * MATSZ;
    __shared__ float sA[64][65];
    const int t = threadIdx.x;                // 64 threads
    for (int r = t; r < 64; r += 64)
        for (int c = 0; c <= r; ++c)
            sA[r][c] = A[(size_t)(s * 64 + r) * 512 + s * 64 + c];
    __syncthreads();
    for (int j = 0; j < 64; ++j) {
        if (t == 0) sA[j][j] = sqrtf(sA[j][j]);
        __syncthreads();
        const float dinv = 1.f / sA[j][j];
        for (int i = j + 1 + t; i < 64; i += 64) sA[i][j] *= dinv;
        __syncthreads();
        for (int r = j + 1 + t; r < 64; r += 64) {
            const float lrj = sA[r][j];
            for (int c = j + 1; c <= r; ++c) sA[r][c] -= lrj * sA[c][j];
        }
        __syncthreads();
    }
    for (int r = t; r < 64; r += 64)
        for (int c = 0; c <= r; ++c)
            A[(size_t)(s * 64 + r) * 512 + s * 64 + c] = sA[r][c];
}

__global__ void trsm_panel(int s) {
    const int mat = blockIdx.y;
    float* A = g_cov + (size_t)mat * MATSZ;
    __shared__ float L11[64][65];
    __shared__ float sx[64][65];
    const int t = threadIdx.x;                // 64 threads, one row each
    for (int r = t; r < 64; r += 64)
        for (int c = 0; c <= r; ++c)
            L11[r][c] = A[(size_t)(s * 64 + r) * 512 + s * 64 + c];
    const int grow = (s + 1) * 64 + blockIdx.x * 64 + t;
    for (int k = 0; k < 64; ++k) sx[t][k] = A[(size_t)grow * 512 + s * 64 + k];
    __syncthreads();
    for (int j = 0; j < 64; ++j) {
        const float xj = sx[t][j] / L11[j][j];
        sx[t][j] = xj;
        for (int k = j + 1; k < 64; ++k) sx[t][k] -= L11[k][j] * xj;
    }
    for (int k = 0; k < 64; ++k) A[(size_t)grow * 512 + s * 64 + k] = sx[t][k];
}

__global__ void __launch_bounds__(256) syrk_update(int s) {
    const int ti = blockIdx.x, tj = blockIdx.y, mat = blockIdx.z;
    if (ti < tj) return;
    float* A = g_cov + (size_t)mat * MATSZ;
    const int base = (s + 1) * 64;
    const int R0 = base + ti * 64, C0 = base + tj * 64;
    __shared__ float sa[64][68];
    __shared__ float sb[64][68];
    const int t = threadIdx.x;
    {
        const int row = t >> 2, kq = t & 3;
        #pragma unroll
        for (int i2 = 0; i2 < 4; ++i2) {
            const int k = kq * 16 + i2 * 4;
            float4 va = *(const float4*)&A[(size_t)(R0 + row) * 512 + s * 64 + k];
            sa[k + 0][row] = va.x; sa[k + 1][row] = va.y; sa[k + 2][row] = va.z; sa[k + 3][row] = va.w;
            float4 vb = *(const float4*)&A[(size_t)(C0 + row) * 512 + s * 64 + k];
            sb[k + 0][row] = vb.x; sb[k + 1][row] = vb.y; sb[k + 2][row] = vb.z; sb[k + 3][row] = vb.w;
        }
    }
    __syncthreads();
    const int i0 = (t >> 4) << 2, j0 = (t & 15) << 2;
    float acc[4][4];
    #pragma unroll
    for (int i = 0; i < 4; ++i)
        #pragma unroll
        for (int j = 0; j < 4; ++j) acc[i][j] = 0.f;
    #pragma unroll 8
    for (int k = 0; k < 64; ++k) {
        float4 a = *(const float4*)&sa[k][i0];
        float4 b = *(const float4*)&sb[k][j0];
        float av[4] = {a.x, a.y, a.z, a.w}, bv[4] = {b.x, b.y, b.z, b.w};
        #pragma unroll
        for (int i = 0; i < 4; ++i)
            #pragma unroll
            for (int j = 0; j < 4; ++j) acc[i][j] += av[i] * bv[j];
    }
    #pragma unroll
    for (int i = 0; i < 4; ++i) {
        const int li = i0 + i;
        #pragma unroll
        for (int j = 0; j < 4; ++j) {
            const int lj = j0 + j;
            if (ti != tj || li >= lj)
                A[(size_t)(R0 + li) * 512 + C0 + lj] -= acc[i][j];
        }
    }
}

__global__ void zero_upper() {
    const int g = blockIdx.x;                 // 16*512 rows
    const int mat = g >> 9, i = g & 511;
    float* row = g_cov + (size_t)mat * MATSZ + (size_t)i * 512;
    for (int j = i + 1 + threadIdx.x; j < 512; j += 64) row[j] = 0.f;
}

// ---------------- 4) inv(Lc): one warp per column (content mats only) ----------------
__global__ void __launch_bounds__(256) trinv_kernel() {
    __shared__ float sy[8][512];
    const int w = threadIdx.x >> 5, lane = threadIdx.x & 31;
    const int g = blockIdx.x * 8 + w;         // 0..4095
    const int mat = g >> 9;                   // 0..7
    const int j = g & 511;
    const float* L = g_cov + (size_t)mat * MATSZ;
    float* IC = g_inv + (size_t)mat * MATSZ;
    float* y = sy[w];
    for (int i = lane; i < j; i += 32) IC[(size_t)i * 512 + j] = 0.f;   // strict upper of column
    const float yj = 1.f / L[(size_t)j * 512 + j];
    if (lane == 0) { y[j] = yj; IC[(size_t)j * 512 + j] = yj; }
    __syncwarp();
    for (int i = j + 1; i < 512; ++i) {
        const float* Lrow = L + (size_t)i * 512;
        float acc = 0.f;
        for (int k = j + lane; k < i; k += 32) acc += Lrow[k] * y[k];
        #pragma unroll
        for (int o = 16; o; o >>= 1) acc += __shfl_xor_sync(0xffffffffu, acc, o);
        const float yi = -acc / Lrow[i];
        if (lane == 0) { y[i] = yi; IC[(size_t)i * 512 + j] = yi; }
        __syncwarp();
    }
}

// ---------------- 5) generic NN GEMM (128x128x16 tiles, 8x8 microtile) ----------------
__global__ void __launch_bounds__(256) gemm_nn(const float* __restrict__ Ab,
                                               const float* __restrict__ Bb,
                                               float* __restrict__ Cb,
                                               int lda, int ldb, int ldc, int K,
                                               size_t sA, size_t sB, size_t sC,
                                               const float* __restrict__ bias) {
    const int bn = blockIdx.x, bm = blockIdx.y, bz = blockIdx.z;
    const float* A = Ab + (size_t)bz * sA;
    const float* B = Bb + (size_t)bz * sB;
    float* C = Cb + (size_t)bz * sC;

    __shared__ float As[2][16][TPAD];
    __shared__ float Bs[2][16][128];

    const int t = threadIdx.x;
    const int arow = t & 127, akg = t >> 7;
    const float* aptr = A + (size_t)(bm * 128 + arow) * lda + akg * 8;
    const int bkr = t >> 5, bc = (t & 31) << 2;
    const float* bptr = B + (size_t)bkr * ldb + bn * 128 + bc;
    const int m0 = (t >> 4) << 3, n0 = (t & 15) << 3;

    float acc[8][8];
    #pragma unroll
    for (int i = 0; i < 8; ++i)
        #pragma unroll
        for (int j = 0; j < 8; ++j) acc[i][j] = 0.f;

    const int NT = K / 16;
    {   // prefetch tile 0
        float av[8];
        *(float4*)&av[0] = *(const float4*)(aptr);
        *(float4*)&av[4] = *(const float4*)(aptr + 4);
        const int kb = akg * 8;
        #pragma unroll
        for (int c = 0; c < 8; ++c) As[0][kb + c][arow] = av[c];
        float4 v0 = *(const float4*)(bptr);
        float4 v1 = *(const float4*)(bptr + (size_t)8 * ldb);
        *(float4*)&Bs[0][bkr][bc]     = v0;
        *(float4*)&Bs[0][bkr + 8][bc] = v1;
    }
    __syncthreads();

    for (int kt = 0; kt < NT; ++kt) {
        const int cur = kt & 1;
        if (kt + 1 < NT) {
            const int nb = cur ^ 1;
            float av[8];
            const float* ap = aptr + (kt + 1) * 16;
            *(float4*)&av[0] = *(const float4*)(ap);
            *(float4*)&av[4] = *(const float4*)(ap + 4);
            const int kb = akg * 8;
            #pragma unroll
            for (int c = 0; c < 8; ++c) As[nb][kb + c][arow] = av[c];
            const float* bp = bptr + (size_t)((kt + 1) * 16) * ldb;
            float4 v0 = *(const float4*)(bp);
            float4 v1 = *(const float4*)(bp + (size_t)8 * ldb);
            *(float4*)&Bs[nb][bkr][bc]     = v0;
            *(float4*)&Bs[nb][bkr + 8][bc] = v1;
        }
        #pragma unroll
        for (int k = 0; k < 16; ++k) {
            float a[8], b[8];
            *(float4*)&a[0] = *(const float4*)&As[cur][k][m0];
            *(float4*)&a[4] = *(const float4*)&As[cur][k][m0 + 4];
            *(float4*)&b[0] = *(const float4*)&Bs[cur][k][n0];
            *(float4*)&b[4] = *(const float4*)&Bs[cur][k][n0 + 4];
            #pragma unroll
            for (int i = 0; i < 8; ++i)
                #pragma unroll
                for (int j = 0; j < 8; ++j) acc[i][j] += a[i] * b[j];
        }
        __syncthreads();
    }

    #pragma unroll
    for (int i = 0; i < 8; ++i) {
        const int gi = bm * 128 + m0 + i;
        const float bv = bias ? bias[(size_t)bz * 512 + gi] : 0.f;
        #pragma unroll
        for (int j = 0; j < 8; ++j)
            C[(size_t)gi * ldc + bn * 128 + n0 + j] = acc[i][j] + bv;
    }
}

// ---------------- 6) bias = ms - T @ mc ----------------
__global__ void bias_kernel() {
    const int w = threadIdx.x >> 5, lane = threadIdx.x & 31;
    const int g = blockIdx.x * 8 + w;         // 0..4095
    const int b = g >> 9, i = g & 511;
    const float* Trow = g_T + (size_t)b * MATSZ + (size_t)i * 512;
    const float* mc = g_mean + b * 512;
    float acc = 0.f;
    for (int k = lane; k < 512; k += 32) acc += Trow[k] * mc[k];
    #pragma unroll
    for (int o = 16; o; o >>= 1) acc += __shfl_xor_sync(0xffffffffu, acc, o);
    if (lane == 0) g_bias[g] = g_mean[(8 + b) * 512 + i] - acc;
}

// ---------------- launcher ----------------
extern "C" void kernel_launch(void* const* d_in, const int* in_sizes, int n_in,
                              void* d_out, int out_size) {
    const float* cont = (const float*)d_in[0];
    const float* styl = (const float*)d_in[1];
    float* out = (float*)d_out;

    float* covp; cudaGetSymbolAddress((void**)&covp, g_cov);
    float* invp; cudaGetSymbolAddress((void**)&invp, g_inv);
    float* Tp;   cudaGetSymbolAddress((void**)&Tp,   g_T);
    float* biasp;cudaGetSymbolAddress((void**)&biasp,g_bias);

    // 1) means for content & style rows
    mean_kernel<<<NMAT * 512, 256>>>(cont, styl);

    // 2) covariance via symmetric Gram
    gram_kernel<<<dim3(4, 4, NMAT), 256>>>(cont, styl);

    // 3) blocked Cholesky, 8 steps of 64
    for (int s = 0; s < 8; ++s) {
        chol_diag<<<NMAT, 64>>>(s);
        const int nrem = 512 - (s + 1) * 64;
        if (nrem > 0) {
            trsm_panel<<<dim3(nrem / 64, NMAT), 64>>>(s);
            syrk_update<<<dim3(nrem / 64, nrem / 64, NMAT), 256>>>(s);
        }
    }
    zero_upper<<<NMAT * 512, 64>>>();

    // 4) inv(Lc)
    trinv_kernel<<<512, 256>>>();

    // 5) T = Ls @ inv(Lc)   (batched 512x512x512)
    gemm_nn<<<dim3(4, 4, BB), 256>>>(covp + (size_t)8 * MATSZ, invp, Tp,
                                     512, 512, 512, 512,
                                     (size_t)MATSZ, (size_t)MATSZ, (size_t)MATSZ,
                                     nullptr);

    // 6) bias = ms - T @ mc
    bias_kernel<<<512, 256>>>();

    // 7) out = T @ xc + bias   (batched 512x4096x512)
    gemm_nn<<<dim3(32, 4, BB), 256>>>(Tp, cont, out,
                                      512, 4096, 4096, 512,
                                      (size_t)MATSZ, (size_t)(512ull * 4096ull),
                                      (size_t)(512ull * 4096ull),
                                      biasp);
}